// round 9
// baseline (speedup 1.0000x reference)
#include <cuda_runtime.h>
#include <cstdint>

#define B_SZ   32
#define RESN   100
#define ITERS  1000
#define KSPLIT 16

typedef unsigned long long ull;

// -------- scratch (device globals; no allocation allowed) ----------
__device__ float g_h1[B_SZ * 128];
__device__ float g_h2[B_SZ * 256];
__device__ float g_h3[B_SZ * 512];
__device__ float g_part[KSPLIT * B_SZ * 10000];

// ---------------------- f32x2 helpers ------------------------------
__device__ __forceinline__ ull pack2(float lo, float hi) {
    ull r; unsigned a = __float_as_uint(lo), b = __float_as_uint(hi);
    asm("mov.b64 %0, {%1,%2};" : "=l"(r) : "r"(a), "r"(b));
    return r;
}
__device__ __forceinline__ float lo2(ull v) {
    unsigned a, b;
    asm("mov.b64 {%0,%1}, %2;" : "=r"(a), "=r"(b) : "l"(v));
    return __uint_as_float(a);
}
__device__ __forceinline__ float hi2(ull v) {
    unsigned a, b;
    asm("mov.b64 {%0,%1}, %2;" : "=r"(a), "=r"(b) : "l"(v));
    return __uint_as_float(b);
}
__device__ __forceinline__ ull shift_pair(ull a, ull b) {   // (hi a, lo b)
    unsigned a0, a1, b0, b1;
    asm("mov.b64 {%0,%1}, %2;" : "=r"(a0), "=r"(a1) : "l"(a));
    asm("mov.b64 {%0,%1}, %2;" : "=r"(b0), "=r"(b1) : "l"(b));
    ull r;
    asm("mov.b64 %0, {%1,%2};" : "=l"(r) : "r"(a1), "r"(b0));
    return r;
}
__device__ __forceinline__ ull fma2(ull a, ull b, ull c) {
    ull d;
    asm("fma.rn.f32x2 %0, %1, %2, %3;" : "=l"(d) : "l"(a), "l"(b), "l"(c));
    return d;
}
__device__ __forceinline__ ull mul2(ull a, ull b) {
    ull d;
    asm("mul.rn.f32x2 %0, %1, %2;" : "=l"(d) : "l"(a), "l"(b));
    return d;
}

// -------------------- MLP layers 1..3 (small) ----------------------
__global__ void fc1_kernel(const float* __restrict__ pores,
                           const float* __restrict__ W,
                           const float* __restrict__ bias) {
    int idx = blockIdx.x * blockDim.x + threadIdx.x;
    if (idx >= B_SZ * 128) return;
    int b = idx >> 7, j = idx & 127;
    float acc = bias[j];
#pragma unroll
    for (int k = 0; k < 25; k++)
        acc = fmaf(pores[b * 25 + k], W[k * 128 + j], acc);
    g_h1[idx] = fmaxf(acc, 0.0f);
}

__global__ void fc2_kernel(const float* __restrict__ W,
                           const float* __restrict__ bias) {
    int idx = blockIdx.x * blockDim.x + threadIdx.x;
    if (idx >= B_SZ * 256) return;
    int b = idx >> 8, j = idx & 255;
    float acc = bias[j];
#pragma unroll 8
    for (int k = 0; k < 128; k++)
        acc = fmaf(g_h1[b * 128 + k], W[k * 256 + j], acc);
    g_h2[idx] = fmaxf(acc, 0.0f);
}

__global__ void fc3_kernel(const float* __restrict__ W,
                           const float* __restrict__ bias) {
    int idx = blockIdx.x * blockDim.x + threadIdx.x;
    if (idx >= B_SZ * 512) return;
    int b = idx >> 9, j = idx & 511;
    float acc = bias[j];
#pragma unroll 8
    for (int k = 0; k < 256; k++)
        acc = fmaf(g_h2[b * 256 + k], W[k * 512 + j], acc);
    g_h3[idx] = fmaxf(acc, 0.0f);
}

// ---------------- fc4 stage 1: split-K partial sums ----------------
__global__ __launch_bounds__(128) void fc4_partial_kernel(
    const float* __restrict__ W)     // [512,10000]
{
    __shared__ float h3s[B_SZ * 32];
    int k0 = blockIdx.y * 32;
    for (int i = threadIdx.x; i < B_SZ * 32; i += blockDim.x) {
        int q = i >> 5, kk = i & 31;
        h3s[i] = g_h3[q * 512 + k0 + kk];
    }
    __syncthreads();

    int o = blockIdx.x * blockDim.x + threadIdx.x;
    if (o >= RESN * RESN) return;

    float acc[B_SZ];
#pragma unroll
    for (int q = 0; q < B_SZ; q++) acc[q] = 0.0f;

#pragma unroll
    for (int kk = 0; kk < 32; kk += 4) {
        float w0 = W[(k0 + kk + 0) * 10000 + o];
        float w1 = W[(k0 + kk + 1) * 10000 + o];
        float w2 = W[(k0 + kk + 2) * 10000 + o];
        float w3 = W[(k0 + kk + 3) * 10000 + o];
#pragma unroll
        for (int q = 0; q < B_SZ; q++) {
            acc[q] = fmaf(h3s[q * 32 + kk + 0], w0, acc[q]);
            acc[q] = fmaf(h3s[q * 32 + kk + 1], w1, acc[q]);
            acc[q] = fmaf(h3s[q * 32 + kk + 2], w2, acc[q]);
            acc[q] = fmaf(h3s[q * 32 + kk + 3], w3, acc[q]);
        }
    }

    float* dst = g_part + blockIdx.y * (B_SZ * 10000);
#pragma unroll
    for (int q = 0; q < B_SZ; q++)
        dst[q * 10000 + o] = acc[q];
}

// -------- fc4 stage 2: reduce + bias + residual + clamp ------------
__global__ __launch_bounds__(128) void fc4_final_kernel(
    const float* __restrict__ bias,
    const float* __restrict__ pores,
    float* __restrict__ cond)
{
    int o = blockIdx.x * blockDim.x + threadIdx.x;
    if (o >= RESN * RESN) return;
    int i = o / RESN, j = o % RESN;
    int pidx = (i / 20) * 5 + (j / 20);
    float bb = bias[o];
    int q0 = blockIdx.y * 4;
#pragma unroll
    for (int qq = 0; qq < 4; qq++) {
        int q = q0 + qq;
        float s = bb;
#pragma unroll
        for (int p = 0; p < KSPLIT; p++)
            s += g_part[p * (B_SZ * 10000) + q * 10000 + o];
        float base = 1.0f - pores[q * 25 + pidx];
        cond[q * 10000 + o] = fmaxf(s + base, 0.01f);
    }
}

// ----- Jacobi: warp strips + shuffle rows, SMEM cols only -----------
// 10 warps (320 thr). Warp w owns cols [10w,10w+10); lane l (0..24)
// owns rows [4l,4l+4) as P[4][5] f32x2. Lanes 25-31 duplicate lane 24
// (clamped addressing, results never stored). N/S halo rows exchanged
// by warp shuffle of register state; only W/E columns (float4 each)
// go through SMEM (double-buffered, 1 barrier/iter).
__global__ __launch_bounds__(320, 1)
void jacobi_kernel(const float* __restrict__ cond,   // [32,10000]
                   float* __restrict__ kappa)        // [32]
{
    // CL/CR col arrays: [buf][slot=tid] float4
    __shared__ float4 CL[2][320];
    __shared__ float4 CR[2][320];
    __shared__ float partial[10];

    int b = blockIdx.x;
    const float* k = cond + b * 10000;
    int tid  = threadIdx.x;
    int w    = tid >> 5;               // warp / col-strip 0..9
    int lane = tid & 31;
    int lc   = (lane < 25) ? lane : 24; // clamped band for lanes 25-31
    int r0 = lc * 4, c0 = w * 10;

    const ull ONE2 = 0x3F8000003F800000ULL;

    ull cN[4][5], cS[4][5], cW[4][5], cE[4][5], P[4][5];

    // ---- coefficients ----
#pragma unroll
    for (int i = 0; i < 4; i++) {
        int rg = r0 + i;
        int rm = (rg == 0)  ? 0  : rg - 1;
        int rp = (rg == 99) ? 99 : rg + 1;
        float fN[10], fS[10], fW[10], fE[10];
#pragma unroll
        for (int j = 0; j < 10; j++) {
            int c  = c0 + j;
            int cm = (c == 0)  ? 0  : c - 1;
            int cp = (c == 99) ? 99 : c + 1;
            float kc = k[rg * 100 + c];
            float kn = 0.5f * (kc + k[rm * 100 + c]);
            float ks = 0.5f * (kc + k[rp * 100 + c]);
            float kw = 0.5f * (kc + k[rg * 100 + cm]);
            float ke = 0.5f * (kc + k[rg * 100 + cp]);
            float inv = 1.0f / (kn + ks + kw + ke + 1e-12f);
            fN[j] = kn * inv; fS[j] = ks * inv;
            fW[j] = kw * inv; fE[j] = ke * inv;
        }
#pragma unroll
        for (int p = 0; p < 5; p++) {
            cN[i][p] = pack2(fN[2*p], fN[2*p+1]);
            cS[i][p] = pack2(fS[2*p], fS[2*p+1]);
            cW[i][p] = pack2(fW[2*p], fW[2*p+1]);
            cE[i][p] = pack2(fE[2*p], fE[2*p+1]);
        }
    }

    // ---- initial field + buffer-0 cols ----
#pragma unroll
    for (int i = 0; i < 4; i++) {
        float tv = 1.0f - (float)(r0 + i) * (1.0f / 99.0f);
#pragma unroll
        for (int p = 0; p < 5; p++) P[i][p] = pack2(tv, tv);
    }
    CL[0][tid] = make_float4(lo2(P[0][0]), lo2(P[1][0]), lo2(P[2][0]), lo2(P[3][0]));
    CR[0][tid] = make_float4(hi2(P[0][4]), hi2(P[1][4]), hi2(P[2][4]), hi2(P[3][4]));
    __syncthreads();

    int wslot = ((w == 0) ? w : w - 1) * 32 + lane;   // west neighbor (value overridden for w==0)
    int eslot = ((w == 9) ? w : w + 1) * 32 + lane;

    int cur = 0;
    for (int it = 0; it < ITERS; ++it) {
        // ---- W/E halos from SMEM (old) ----
        float4 wf = CR[cur][wslot];
        float4 ef = CL[cur][eslot];
        float west[4] = {wf.x, wf.y, wf.z, wf.w};
        float east[4] = {ef.x, ef.y, ef.z, ef.w};

        // ---- N/S halos by warp shuffle (old register state) ----
        ull nh[5], sh[5];
#pragma unroll
        for (int p = 0; p < 5; p++) {
            nh[p] = __shfl_up_sync(0xffffffff,   P[3][p], 1);
            sh[p] = __shfl_down_sync(0xffffffff, P[0][p], 1);
        }
        if (lane == 0) {
#pragma unroll
            for (int p = 0; p < 5; p++) nh[p] = ONE2;     // T=1 top Dirichlet
        }
        if (lane >= 24) {
#pragma unroll
            for (int p = 0; p < 5; p++) sh[p] = 0;        // T=0 bottom Dirichlet
        }

        ull pn0 = nh[0], pn1 = nh[1], pn2 = nh[2], pn3 = nh[3], pn4 = nh[4];
#pragma unroll
        for (int i = 0; i < 4; i++) {
            ull o0 = P[i][0], o1 = P[i][1], o2 = P[i][2], o3 = P[i][3], o4 = P[i][4];
            ull s0, s1, s2, s3, s4;
            if (i < 3) { s0 = P[i+1][0]; s1 = P[i+1][1]; s2 = P[i+1][2];
                         s3 = P[i+1][3]; s4 = P[i+1][4]; }
            else       { s0 = sh[0]; s1 = sh[1]; s2 = sh[2]; s3 = sh[3]; s4 = sh[4]; }

            float left  = (w == 0) ? lo2(o0) : west[i];   // insulated sides
            float right = (w == 9) ? hi2(o4) : east[i];

            ull W0 = pack2(left, lo2(o0));
            ull E0 = shift_pair(o0, o1);
            ull E1 = shift_pair(o1, o2);
            ull E2 = shift_pair(o2, o3);
            ull E3 = shift_pair(o3, o4);
            ull E4 = pack2(hi2(o4), right);

            P[i][0] = fma2(cN[i][0], pn0, fma2(cS[i][0], s0,
                      fma2(cW[i][0], W0, mul2(cE[i][0], E0))));
            P[i][1] = fma2(cN[i][1], pn1, fma2(cS[i][1], s1,
                      fma2(cW[i][1], E0, mul2(cE[i][1], E1))));
            P[i][2] = fma2(cN[i][2], pn2, fma2(cS[i][2], s2,
                      fma2(cW[i][2], E1, mul2(cE[i][2], E2))));
            P[i][3] = fma2(cN[i][3], pn3, fma2(cS[i][3], s3,
                      fma2(cW[i][3], E2, mul2(cE[i][3], E3))));
            P[i][4] = fma2(cN[i][4], pn4, fma2(cS[i][4], s4,
                      fma2(cW[i][4], E3, mul2(cE[i][4], E4))));

            pn0 = o0; pn1 = o1; pn2 = o2; pn3 = o3; pn4 = o4;
        }

        // ---- publish new W/E cols ----
        int nxt = cur ^ 1;
        CL[nxt][tid] = make_float4(lo2(P[0][0]), lo2(P[1][0]), lo2(P[2][0]), lo2(P[3][0]));
        CR[nxt][tid] = make_float4(hi2(P[0][4]), hi2(P[1][4]), hi2(P[2][4]), hi2(P[3][4]));

        __syncthreads();
        cur = nxt;
    }

    // kappa = 2 * sum_c k[0,c] * (1 - T[0,c]); lane 0 of each warp holds row 0
    if (lane == 0) {
        float p = 0.0f;
#pragma unroll
        for (int m = 0; m < 5; m++) {
            p += k[c0 + 2*m]     * (1.0f - lo2(P[0][m]));
            p += k[c0 + 2*m + 1] * (1.0f - hi2(P[0][m]));
        }
        partial[w] = p;
    }
    __syncthreads();
    if (tid == 0) {
        float sum = 0.0f;
#pragma unroll
        for (int q = 0; q < 10; q++) sum += partial[q];
        kappa[b] = 2.0f * sum;
    }
}

// --------------------------- launcher ------------------------------
extern "C" void kernel_launch(void* const* d_in, const int* in_sizes, int n_in,
                              void* d_out, int out_size) {
    const float* pores = (const float*)d_in[0];
    const float* W1 = (const float*)d_in[1];
    const float* b1 = (const float*)d_in[2];
    const float* W2 = (const float*)d_in[3];
    const float* b2 = (const float*)d_in[4];
    const float* W3 = (const float*)d_in[5];
    const float* b3 = (const float*)d_in[6];
    const float* W4 = (const float*)d_in[7];
    const float* b4 = (const float*)d_in[8];

    float* out   = (float*)d_out;
    float* kappa = out;          // [32]
    float* cond  = out + B_SZ;   // [32,100,100]

    fc1_kernel<<<(B_SZ * 128 + 255) / 256, 256>>>(pores, W1, b1);
    fc2_kernel<<<(B_SZ * 256 + 255) / 256, 256>>>(W2, b2);
    fc3_kernel<<<(B_SZ * 512 + 255) / 256, 256>>>(W3, b3);
    dim3 g4((10000 + 127) / 128, KSPLIT);
    fc4_partial_kernel<<<g4, 128>>>(W4);
    dim3 g5((10000 + 127) / 128, B_SZ / 4);
    fc4_final_kernel<<<g5, 128>>>(b4, pores, cond);
    jacobi_kernel<<<B_SZ, 320>>>(cond, kappa);
}

// round 10
// speedup vs baseline: 1.9099x; 1.9099x over previous
#include <cuda_runtime.h>
#include <cstdint>

#define B_SZ   32
#define RESN   100
#define ITERS  1000
#define KSPLIT 16

typedef unsigned long long ull;

// Jacobi: 500 threads, 4 rows x 5 cols per thread.
// Per-buffer SMEM layout (words):
//   TOPP 0..2000 (ull2/thread), TOPS 2000..2500 (float/thread)
//   BOTP 2500..4500,            BOTS 4500..5000
//   CL   5000..7000 (float4),   CR   7000..9000 (float4)
#define OFF_TOPS 2000
#define OFF_BOTP 2500
#define OFF_BOTS 4500
#define OFF_CL   5000
#define OFF_CR   7000
#define BUFW     9000

// -------- scratch (device globals; no allocation allowed) ----------
__device__ float g_h1[B_SZ * 128];
__device__ float g_h2[B_SZ * 256];
__device__ float g_h3[B_SZ * 512];
__device__ float g_part[KSPLIT * B_SZ * 10000];

// ---------------------- f32x2 helpers ------------------------------
__device__ __forceinline__ ull pack2(float lo, float hi) {
    ull r; unsigned a = __float_as_uint(lo), b = __float_as_uint(hi);
    asm("mov.b64 %0, {%1,%2};" : "=l"(r) : "r"(a), "r"(b));
    return r;
}
__device__ __forceinline__ float lo2(ull v) {
    unsigned a, b;
    asm("mov.b64 {%0,%1}, %2;" : "=r"(a), "=r"(b) : "l"(v));
    return __uint_as_float(a);
}
__device__ __forceinline__ float hi2(ull v) {
    unsigned a, b;
    asm("mov.b64 {%0,%1}, %2;" : "=r"(a), "=r"(b) : "l"(v));
    return __uint_as_float(b);
}
__device__ __forceinline__ ull shift_pair(ull a, ull b) {   // (hi a, lo b)
    unsigned a0, a1, b0, b1;
    asm("mov.b64 {%0,%1}, %2;" : "=r"(a0), "=r"(a1) : "l"(a));
    asm("mov.b64 {%0,%1}, %2;" : "=r"(b0), "=r"(b1) : "l"(b));
    ull r;
    asm("mov.b64 %0, {%1,%2};" : "=l"(r) : "r"(a1), "r"(b0));
    return r;
}
__device__ __forceinline__ ull fma2(ull a, ull b, ull c) {
    ull d;
    asm("fma.rn.f32x2 %0, %1, %2, %3;" : "=l"(d) : "l"(a), "l"(b), "l"(c));
    return d;
}
__device__ __forceinline__ ull mul2(ull a, ull b) {
    ull d;
    asm("mul.rn.f32x2 %0, %1, %2;" : "=l"(d) : "l"(a), "l"(b));
    return d;
}

// -------------------- MLP layers 1..3 (small) ----------------------
__global__ void fc1_kernel(const float* __restrict__ pores,
                           const float* __restrict__ W,
                           const float* __restrict__ bias) {
    int idx = blockIdx.x * blockDim.x + threadIdx.x;
    if (idx >= B_SZ * 128) return;
    int b = idx >> 7, j = idx & 127;
    float acc = bias[j];
#pragma unroll
    for (int k = 0; k < 25; k++)
        acc = fmaf(pores[b * 25 + k], W[k * 128 + j], acc);
    g_h1[idx] = fmaxf(acc, 0.0f);
}

__global__ void fc2_kernel(const float* __restrict__ W,
                           const float* __restrict__ bias) {
    int idx = blockIdx.x * blockDim.x + threadIdx.x;
    if (idx >= B_SZ * 256) return;
    int b = idx >> 8, j = idx & 255;
    float acc = bias[j];
#pragma unroll 8
    for (int k = 0; k < 128; k++)
        acc = fmaf(g_h1[b * 128 + k], W[k * 256 + j], acc);
    g_h2[idx] = fmaxf(acc, 0.0f);
}

__global__ void fc3_kernel(const float* __restrict__ W,
                           const float* __restrict__ bias) {
    int idx = blockIdx.x * blockDim.x + threadIdx.x;
    if (idx >= B_SZ * 512) return;
    int b = idx >> 9, j = idx & 511;
    float acc = bias[j];
#pragma unroll 8
    for (int k = 0; k < 256; k++)
        acc = fmaf(g_h2[b * 256 + k], W[k * 512 + j], acc);
    g_h3[idx] = fmaxf(acc, 0.0f);
}

// ---------------- fc4 stage 1: split-K partial sums ----------------
__global__ __launch_bounds__(128) void fc4_partial_kernel(
    const float* __restrict__ W)     // [512,10000]
{
    __shared__ float h3s[B_SZ * 32];
    int k0 = blockIdx.y * 32;
    for (int i = threadIdx.x; i < B_SZ * 32; i += blockDim.x) {
        int q = i >> 5, kk = i & 31;
        h3s[i] = g_h3[q * 512 + k0 + kk];
    }
    __syncthreads();

    int o = blockIdx.x * blockDim.x + threadIdx.x;
    if (o >= RESN * RESN) return;

    float acc[B_SZ];
#pragma unroll
    for (int q = 0; q < B_SZ; q++) acc[q] = 0.0f;

#pragma unroll
    for (int kk = 0; kk < 32; kk += 4) {
        float w0 = W[(k0 + kk + 0) * 10000 + o];
        float w1 = W[(k0 + kk + 1) * 10000 + o];
        float w2 = W[(k0 + kk + 2) * 10000 + o];
        float w3 = W[(k0 + kk + 3) * 10000 + o];
#pragma unroll
        for (int q = 0; q < B_SZ; q++) {
            acc[q] = fmaf(h3s[q * 32 + kk + 0], w0, acc[q]);
            acc[q] = fmaf(h3s[q * 32 + kk + 1], w1, acc[q]);
            acc[q] = fmaf(h3s[q * 32 + kk + 2], w2, acc[q]);
            acc[q] = fmaf(h3s[q * 32 + kk + 3], w3, acc[q]);
        }
    }

    float* dst = g_part + blockIdx.y * (B_SZ * 10000);
#pragma unroll
    for (int q = 0; q < B_SZ; q++)
        dst[q * 10000 + o] = acc[q];
}

// -------- fc4 stage 2: reduce + bias + residual + clamp ------------
__global__ __launch_bounds__(128) void fc4_final_kernel(
    const float* __restrict__ bias,
    const float* __restrict__ pores,
    float* __restrict__ cond)
{
    int o = blockIdx.x * blockDim.x + threadIdx.x;
    if (o >= RESN * RESN) return;
    int i = o / RESN, j = o % RESN;
    int pidx = (i / 20) * 5 + (j / 20);
    float bb = bias[o];
    int q0 = blockIdx.y * 4;
#pragma unroll
    for (int qq = 0; qq < 4; qq++) {
        int q = q0 + qq;
        float s = bb;
#pragma unroll
        for (int p = 0; p < KSPLIT; p++)
            s += g_part[p * (B_SZ * 10000) + q * 10000 + o];
        float base = 1.0f - pores[q * 25 + pidx];
        cond[q * 10000 + o] = fmaxf(s + base, 0.01f);
    }
}

// ------ Jacobi: 4x5 register tiles, 500 threads, dense edges --------
// band = tid/20 (25 bands x 4 rows), tcol = tid%20 (20 strips x 5 cols).
// Per row: P0=(c0,c1), P1=(c2,c3) f32x2 pairs + C4 scalar.
// Perimeter through dense conflict-free SMEM arrays (see layout above).
__global__ __launch_bounds__(512, 1)
void jacobi_kernel(const float* __restrict__ cond,   // [32,10000]
                   float* __restrict__ kappa)        // [32]
{
    extern __shared__ float sm[];
    float* partial = sm + 2 * BUFW;    // 20 floats

    int b = blockIdx.x;
    const float* k = cond + b * 10000;
    int tid  = threadIdx.x;
    bool act = tid < 500;
    int band = tid / 20;               // 0..24
    int tcol = tid % 20;               // 0..19
    int r0 = band * 4, c0 = tcol * 5;

    const ull ONE2 = 0x3F8000003F800000ULL;

    ull  cN0[4], cN1[4], cS0[4], cS1[4], cW0[4], cW1[4], cE0[4], cE1[4];
    float cN4[4], cS4[4], cW4[4], cE4[4];
    ull  P0[4], P1[4];
    float C4[4];

    if (act) {
        // ---- coefficients ----
#pragma unroll
        for (int i = 0; i < 4; i++) {
            int rg = r0 + i;
            int rm = (rg == 0)  ? 0  : rg - 1;
            int rp = (rg == 99) ? 99 : rg + 1;
            float fN[5], fS[5], fW[5], fE[5];
#pragma unroll
            for (int j = 0; j < 5; j++) {
                int c  = c0 + j;
                int cm = (c == 0)  ? 0  : c - 1;
                int cp = (c == 99) ? 99 : c + 1;
                float kc = k[rg * 100 + c];
                float kn = 0.5f * (kc + k[rm * 100 + c]);
                float ks = 0.5f * (kc + k[rp * 100 + c]);
                float kw = 0.5f * (kc + k[rg * 100 + cm]);
                float ke = 0.5f * (kc + k[rg * 100 + cp]);
                float inv = 1.0f / (kn + ks + kw + ke + 1e-12f);
                fN[j] = kn * inv; fS[j] = ks * inv;
                fW[j] = kw * inv; fE[j] = ke * inv;
            }
            cN0[i] = pack2(fN[0], fN[1]); cN1[i] = pack2(fN[2], fN[3]); cN4[i] = fN[4];
            cS0[i] = pack2(fS[0], fS[1]); cS1[i] = pack2(fS[2], fS[3]); cS4[i] = fS[4];
            cW0[i] = pack2(fW[0], fW[1]); cW1[i] = pack2(fW[2], fW[3]); cW4[i] = fW[4];
            cE0[i] = pack2(fE[0], fE[1]); cE1[i] = pack2(fE[2], fE[3]); cE4[i] = fE[4];
        }

        // ---- initial field + buffer-0 perimeter ----
#pragma unroll
        for (int i = 0; i < 4; i++) {
            float tv = 1.0f - (float)(r0 + i) * (1.0f / 99.0f);
            P0[i] = pack2(tv, tv); P1[i] = pack2(tv, tv); C4[i] = tv;
        }
        ulonglong2 v;
        v.x = P0[0]; v.y = P1[0];
        reinterpret_cast<ulonglong2*>(sm)[tid] = v;
        sm[OFF_TOPS + tid] = C4[0];
        v.x = P0[3]; v.y = P1[3];
        reinterpret_cast<ulonglong2*>(sm + OFF_BOTP)[tid] = v;
        sm[OFF_BOTS + tid] = C4[3];
        reinterpret_cast<float4*>(sm + OFF_CL)[tid] =
            make_float4(lo2(P0[0]), lo2(P0[1]), lo2(P0[2]), lo2(P0[3]));
        reinterpret_cast<float4*>(sm + OFF_CR)[tid] =
            make_float4(C4[0], C4[1], C4[2], C4[3]);
    }
    __syncthreads();

    int cur = 0;
    for (int it = 0; it < ITERS; ++it) {
        if (act) {
            const float* C  = sm + cur * BUFW;
            float*       Nx = sm + (cur ^ 1) * BUFW;

            // ---- halo loads (OLD); clamp addr, override value ----
            int nslot = (band == 0)  ? tid : tid - 20;
            int sslot = (band == 24) ? tid : tid + 20;
            ulonglong2 nv = reinterpret_cast<const ulonglong2*>(C + OFF_BOTP)[nslot];
            float      n4 = (C + OFF_BOTS)[nslot];
            ulonglong2 sv = reinterpret_cast<const ulonglong2*>(C)[sslot];
            float      s4 = (C + OFF_TOPS)[sslot];
            float4 wf = reinterpret_cast<const float4*>(C + OFF_CR)[(tcol == 0)  ? tid : tid - 1];
            float4 ef = reinterpret_cast<const float4*>(C + OFF_CL)[(tcol == 19) ? tid : tid + 1];

            if (band == 0)  { nv.x = ONE2; nv.y = ONE2; n4 = 1.0f; }
            if (band == 24) { sv.x = 0;    sv.y = 0;    s4 = 0.0f; }
            float west[4] = {wf.x, wf.y, wf.z, wf.w};
            float east[4] = {ef.x, ef.y, ef.z, ef.w};

            ull pn0 = nv.x, pn1 = nv.y; float pn4 = n4;
#pragma unroll
            for (int i = 0; i < 4; i++) {
                ull o0 = P0[i], o1 = P1[i]; float o4 = C4[i];
                ull sp0, sp1; float sp4;
                if (i < 3) { sp0 = P0[i + 1]; sp1 = P1[i + 1]; sp4 = C4[i + 1]; }
                else       { sp0 = sv.x;      sp1 = sv.y;      sp4 = s4; }

                float left  = (tcol == 0)  ? lo2(o0) : west[i];
                float right = (tcol == 19) ? o4      : east[i];

                ull W0 = pack2(left, lo2(o0));
                ull E0 = shift_pair(o0, o1);       // (c1, c2)
                ull E1 = pack2(hi2(o1), o4);       // (c3, c4)

                P0[i] = fma2(cN0[i], pn0, fma2(cS0[i], sp0,
                        fma2(cW0[i], W0, mul2(cE0[i], E0))));
                P1[i] = fma2(cN1[i], pn1, fma2(cS1[i], sp1,
                        fma2(cW1[i], E0, mul2(cE1[i], E1))));
                C4[i] = fmaf(cN4[i], pn4, fmaf(cS4[i], sp4,
                        fmaf(cW4[i], hi2(o1), cE4[i] * right)));

                pn0 = o0; pn1 = o1; pn4 = o4;
            }

            // ---- publish new perimeter ----
            ulonglong2 v;
            v.x = P0[0]; v.y = P1[0];
            reinterpret_cast<ulonglong2*>(Nx)[tid] = v;
            (Nx + OFF_TOPS)[tid] = C4[0];
            v.x = P0[3]; v.y = P1[3];
            reinterpret_cast<ulonglong2*>(Nx + OFF_BOTP)[tid] = v;
            (Nx + OFF_BOTS)[tid] = C4[3];
            reinterpret_cast<float4*>(Nx + OFF_CL)[tid] =
                make_float4(lo2(P0[0]), lo2(P0[1]), lo2(P0[2]), lo2(P0[3]));
            reinterpret_cast<float4*>(Nx + OFF_CR)[tid] =
                make_float4(C4[0], C4[1], C4[2], C4[3]);
        }
        __syncthreads();
        cur ^= 1;
    }

    // kappa = 2 * sum_c k[0,c] * (1 - T[0,c]); band 0 holds global row 0
    if (act && band == 0) {
        float p = k[c0 + 0] * (1.0f - lo2(P0[0]))
                + k[c0 + 1] * (1.0f - hi2(P0[0]))
                + k[c0 + 2] * (1.0f - lo2(P1[0]))
                + k[c0 + 3] * (1.0f - hi2(P1[0]))
                + k[c0 + 4] * (1.0f - C4[0]);
        partial[tcol] = p;
    }
    __syncthreads();
    if (tid == 0) {
        float sum = 0.0f;
#pragma unroll
        for (int q = 0; q < 20; q++) sum += partial[q];
        kappa[b] = 2.0f * sum;
    }
}

// --------------------------- launcher ------------------------------
extern "C" void kernel_launch(void* const* d_in, const int* in_sizes, int n_in,
                              void* d_out, int out_size) {
    const float* pores = (const float*)d_in[0];
    const float* W1 = (const float*)d_in[1];
    const float* b1 = (const float*)d_in[2];
    const float* W2 = (const float*)d_in[3];
    const float* b2 = (const float*)d_in[4];
    const float* W3 = (const float*)d_in[5];
    const float* b3 = (const float*)d_in[6];
    const float* W4 = (const float*)d_in[7];
    const float* b4 = (const float*)d_in[8];

    float* out   = (float*)d_out;
    float* kappa = out;          // [32]
    float* cond  = out + B_SZ;   // [32,100,100]

    const int SMEM_JAC = (2 * BUFW + 32) * sizeof(float);  // ~72.1 KB
    cudaFuncSetAttribute(jacobi_kernel, cudaFuncAttributeMaxDynamicSharedMemorySize, SMEM_JAC);

    fc1_kernel<<<(B_SZ * 128 + 255) / 256, 256>>>(pores, W1, b1);
    fc2_kernel<<<(B_SZ * 256 + 255) / 256, 256>>>(W2, b2);
    fc3_kernel<<<(B_SZ * 512 + 255) / 256, 256>>>(W3, b3);
    dim3 g4((10000 + 127) / 128, KSPLIT);
    fc4_partial_kernel<<<g4, 128>>>(W4);
    dim3 g5((10000 + 127) / 128, B_SZ / 4);
    fc4_final_kernel<<<g5, 128>>>(b4, pores, cond);
    jacobi_kernel<<<B_SZ, 500, SMEM_JAC>>>(cond, kappa);
}